// round 9
// baseline (speedup 1.0000x reference)
#include <cuda_runtime.h>
#include <cstdint>

#define NB 16
#define NS 2048
#define NH 512
#define NW 4
#define NL 2
#define NSP (NS + 2*NW)   // 2056
#define LN_EPS 1e-5f

#define BM 128
#define BN 128
#define BK 32
#define NTHREADS 256
#define ASTR 36    // BK + 4  -> conflict-free A fragment loads
#define BSTR 136   // BN + 8  -> conflict-free B fragment loads
#define ASZ (BM*ASTR)
#define BSZ (BK*BSTR)
#define SMEM_BYTES ((2*ASZ + 2*BSZ)*4)   // ping-pong: 71680 B

// Scratch (device globals: allocation-free contract)
__device__ float  g_padded[NB*NSP*NH];
__device__ float  g_lo [NB*NS*NH];
__device__ float  g_ro [NB*NS*NH];
__device__ float  g_hid[NB*NS*NH];
__device__ float2 g_stats[NB*NS];

__device__ __forceinline__ uint32_t f2t(float x){
    uint32_t u; asm("cvt.rna.tf32.f32 %0, %1;" : "=r"(u) : "f"(x)); return u;
}

// Build padded [B, 2056, 512]
__global__ void build_padded_kernel(const float* __restrict__ inp,
                                    const float* __restrict__ lp,
                                    const float* __restrict__ rp){
    int idx = blockIdx.x*blockDim.x + threadIdx.x;
    const int H4 = NH/4;
    const int total = NB*NSP*H4;
    if (idx >= total) return;
    int h4 = idx % H4;
    int r  = (idx / H4) % NSP;
    int b  = idx / (H4*NSP);
    float4 v;
    if (r < NW)            v = reinterpret_cast<const float4*>(lp)[r*H4 + h4];
    else if (r >= NW+NS)   v = reinterpret_cast<const float4*>(rp)[(r-NW-NS)*H4 + h4];
    else                   v = reinterpret_cast<const float4*>(inp)[((size_t)b*NS + (r-NW))*H4 + h4];
    reinterpret_cast<float4*>(g_padded)[idx] = v;
}

// Per-row LN stats: mean + rstd -> g_stats. One warp per 512-float row.
__global__ void ln_stats_kernel(const float* __restrict__ x, float2* __restrict__ st){
    int row  = blockIdx.x*8 + (threadIdx.x >> 5);
    int lane = threadIdx.x & 31;
    const float4* xr = reinterpret_cast<const float4*>(x + (size_t)row*NH);
    float s = 0.f, ss = 0.f;
    #pragma unroll
    for (int i=0;i<4;i++){
        float4 v = xr[lane + i*32];
        s  += v.x + v.y + v.z + v.w;
        ss += v.x*v.x + v.y*v.y + v.z*v.z + v.w*v.w;
    }
    #pragma unroll
    for (int o=16;o>0;o>>=1){
        s  += __shfl_xor_sync(0xffffffff, s,  o);
        ss += __shfl_xor_sync(0xffffffff, ss, o);
    }
    if (lane == 0){
        float mean = s * (1.f/NH);
        float var  = ss * (1.f/NH) - mean*mean;
        st[row] = make_float2(mean, rsqrtf(var + LN_EPS));
    }
}

// tf32 tensor-core GEMM: C[32768, 512] = A[M,K] @ Bw[K,512], ping-pong smem.
// amode: 0 dense A; 1 padded-left view; 2 padded-right view;
//        3 dense A with fused LayerNorm on load (stats + gvec/bvec)
// mode : 0 C = relu(acc+bias)
//        1 r = resid+acc+bias; C=r; scatter to out_all (+ optional out_last), streaming
__global__ __launch_bounds__(NTHREADS) void gemm_tf32_kernel(
    const float* __restrict__ A, const float* __restrict__ Bw, const float* __restrict__ bias,
    float* __restrict__ C, const float* __restrict__ resid,
    float* __restrict__ out_all, float* __restrict__ out_last,
    const float2* __restrict__ stats, const float* __restrict__ gvec, const float* __restrict__ bvec,
    int K, int amode, int mode, int colOff, int layer)
{
    extern __shared__ __align__(16) uint32_t sm[];
    uint32_t* Asb = sm;              // 2 * ASZ
    uint32_t* Bsb = sm + 2*ASZ;      // 2 * BSZ

    const int tid   = threadIdx.x;
    const int lane  = tid & 31;
    const int warp  = tid >> 5;
    const int group = lane >> 2;
    const int tid4  = lane & 3;

    // Per-thread A row pointers + optional LN stats (rows fixed across k-tiles)
    const float* aptr[4];
    float mu[4], rs[4];
    #pragma unroll
    for (int r = 0; r < 4; r++){
        int mrow = blockIdx.y*BM + (tid>>3) + r*32;
        if (amode == 1 || amode == 2){
            int b = mrow >> 11, t = mrow & 2047;
            aptr[r] = A + ((size_t)b*NSP + t + (amode==2 ? (NW+1) : 0)) * NH;
        } else {
            aptr[r] = A + (size_t)mrow * K;
        }
        if (amode == 3){ float2 s = stats[mrow]; mu[r] = s.x; rs[r] = s.y; }
        else           { mu[r] = 0.f; rs[r] = 1.f; }
    }
    const int ak    = (tid & 7) * 4;
    const int bkrow = tid >> 5;
    const int bn    = (tid & 31) * 4;
    const float* bptr = Bw + blockIdx.x*BN + bn;

    float acc[4][4][4];
    #pragma unroll
    for (int i=0;i<4;i++)
      #pragma unroll
      for (int j=0;j<4;j++)
        #pragma unroll
        for (int q=0;q<4;q++) acc[i][j][q]=0.f;

    const int ntiles = K / BK;
    float4 ar[4], br[4], gv, bv;
    gv = make_float4(1.f,1.f,1.f,1.f); bv = make_float4(0.f,0.f,0.f,0.f);

    // ---- Prologue: tile 0 ----
    if (amode == 3){
        gv = *reinterpret_cast<const float4*>(gvec + ak);
        bv = *reinterpret_cast<const float4*>(bvec + ak);
    }
    #pragma unroll
    for (int r=0;r<4;r++) ar[r] = *reinterpret_cast<const float4*>(aptr[r] + ak);
    #pragma unroll
    for (int r=0;r<4;r++) br[r] = *reinterpret_cast<const float4*>(bptr + (size_t)(bkrow + r*8) * NH);
    #pragma unroll
    for (int r=0;r<4;r++){
        if (amode == 3){
            ar[r].x = fmaf(gv.x, (ar[r].x-mu[r])*rs[r], bv.x);
            ar[r].y = fmaf(gv.y, (ar[r].y-mu[r])*rs[r], bv.y);
            ar[r].z = fmaf(gv.z, (ar[r].z-mu[r])*rs[r], bv.z);
            ar[r].w = fmaf(gv.w, (ar[r].w-mu[r])*rs[r], bv.w);
        }
        int row = (tid>>3) + r*32;
        uint4 u = make_uint4(f2t(ar[r].x), f2t(ar[r].y), f2t(ar[r].z), f2t(ar[r].w));
        *reinterpret_cast<uint4*>(&Asb[row*ASTR + ak]) = u;
    }
    #pragma unroll
    for (int r=0;r<4;r++){
        int kr = bkrow + r*8;
        uint4 u = make_uint4(f2t(br[r].x), f2t(br[r].y), f2t(br[r].z), f2t(br[r].w));
        *reinterpret_cast<uint4*>(&Bsb[kr*BSTR + bn]) = u;
    }
    __syncthreads();

    const int wmb = (warp>>2)*64;
    const int wnb = (warp&3)*32;

    int buf = 0;
    for (int kt = 0; kt < ntiles; kt++){
        const bool more = (kt+1 < ntiles);
        if (more){
            int ko = (kt+1)*BK;
            if (amode == 3){
                gv = *reinterpret_cast<const float4*>(gvec + ko + ak);
                bv = *reinterpret_cast<const float4*>(bvec + ko + ak);
            }
            #pragma unroll
            for (int r=0;r<4;r++) ar[r] = *reinterpret_cast<const float4*>(aptr[r] + ko + ak);
            #pragma unroll
            for (int r=0;r<4;r++) br[r] = *reinterpret_cast<const float4*>(bptr + (size_t)(ko + bkrow + r*8) * NH);
        }
        const uint32_t* As = Asb + buf*ASZ;
        const uint32_t* Bs = Bsb + buf*BSZ;
        #pragma unroll
        for (int kk = 0; kk < BK; kk += 8){
            uint32_t af[4][4], bf[4][2];
            #pragma unroll
            for (int mi=0; mi<4; mi++){
                int mr = wmb + mi*16 + group;
                af[mi][0] = As[mr*ASTR     + kk + tid4];
                af[mi][1] = As[(mr+8)*ASTR + kk + tid4];
                af[mi][2] = As[mr*ASTR     + kk + tid4 + 4];
                af[mi][3] = As[(mr+8)*ASTR + kk + tid4 + 4];
            }
            #pragma unroll
            for (int ni=0; ni<4; ni++){
                int nc = wnb + ni*8 + group;
                bf[ni][0] = Bs[(kk + tid4)*BSTR     + nc];
                bf[ni][1] = Bs[(kk + tid4 + 4)*BSTR + nc];
            }
            #pragma unroll
            for (int mi=0; mi<4; mi++)
                #pragma unroll
                for (int ni=0; ni<4; ni++){
                    asm volatile(
                        "mma.sync.aligned.m16n8k8.row.col.f32.tf32.tf32.f32 "
                        "{%0,%1,%2,%3}, {%4,%5,%6,%7}, {%8,%9}, {%0,%1,%2,%3};"
                        : "+f"(acc[mi][ni][0]), "+f"(acc[mi][ni][1]),
                          "+f"(acc[mi][ni][2]), "+f"(acc[mi][ni][3])
                        : "r"(af[mi][0]), "r"(af[mi][1]), "r"(af[mi][2]), "r"(af[mi][3]),
                          "r"(bf[ni][0]), "r"(bf[ni][1]));
                }
        }
        if (more){
            uint32_t* Asn = Asb + (buf^1)*ASZ;
            uint32_t* Bsn = Bsb + (buf^1)*BSZ;
            #pragma unroll
            for (int r=0;r<4;r++){
                if (amode == 3){
                    ar[r].x = fmaf(gv.x, (ar[r].x-mu[r])*rs[r], bv.x);
                    ar[r].y = fmaf(gv.y, (ar[r].y-mu[r])*rs[r], bv.y);
                    ar[r].z = fmaf(gv.z, (ar[r].z-mu[r])*rs[r], bv.z);
                    ar[r].w = fmaf(gv.w, (ar[r].w-mu[r])*rs[r], bv.w);
                }
                int row = (tid>>3) + r*32;
                uint4 u = make_uint4(f2t(ar[r].x), f2t(ar[r].y), f2t(ar[r].z), f2t(ar[r].w));
                *reinterpret_cast<uint4*>(&Asn[row*ASTR + ak]) = u;
            }
            #pragma unroll
            for (int r=0;r<4;r++){
                int kr = bkrow + r*8;
                uint4 u = make_uint4(f2t(br[r].x), f2t(br[r].y), f2t(br[r].z), f2t(br[r].w));
                *reinterpret_cast<uint4*>(&Bsn[kr*BSTR + bn]) = u;
            }
            __syncthreads();
            buf ^= 1;
        }
    }

    // Epilogue
    const int m0 = blockIdx.y*BM + wmb;
    const int n0 = blockIdx.x*BN + wnb;
    #pragma unroll
    for (int mi=0; mi<4; mi++){
        #pragma unroll
        for (int ni=0; ni<4; ni++){
            int rr = m0 + mi*16 + group;
            int cc = n0 + ni*8 + tid4*2;
            #pragma unroll
            for (int q=0;q<4;q++){
                int m = rr + ((q>=2) ? 8 : 0);
                int c = cc + (q&1);
                float v = acc[mi][ni][q] + bias[c];
                size_t ci = (size_t)m*NH + c;
                if (mode == 0){
                    C[ci] = fmaxf(v, 0.f);
                } else {
                    float res = resid[ci] + v;
                    C[ci] = res;
                    int b = m >> 11, s = m & 2047;
                    __stcs(&out_all[(((size_t)layer*NS + s)*NB + b)*(2*NH) + colOff + c], res);
                    if (out_last) __stcs(&out_last[((size_t)m)*(2*NH) + colOff + c], res);
                }
            }
        }
    }
}

extern "C" void kernel_launch(void* const* d_in, const int* in_sizes, int n_in,
                              void* d_out, int out_size){
    const float* inputs = (const float*)d_in[0];
    const float* lp  = (const float*)d_in[1];
    const float* rp  = (const float*)d_in[2];
    const float* Wl  = (const float*)d_in[3];
    const float* bl  = (const float*)d_in[4];
    const float* Wr  = (const float*)d_in[5];
    const float* br_ = (const float*)d_in[6];
    const float* lw1 = (const float*)d_in[7];
    const float* lb1 = (const float*)d_in[8];
    const float* lw2 = (const float*)d_in[9];
    const float* lb2 = (const float*)d_in[10];
    const float* lg  = (const float*)d_in[11];
    const float* lbe = (const float*)d_in[12];
    const float* rw1 = (const float*)d_in[13];
    const float* rb1 = (const float*)d_in[14];
    const float* rw2 = (const float*)d_in[15];
    const float* rb2 = (const float*)d_in[16];
    const float* rg  = (const float*)d_in[17];
    const float* rbe = (const float*)d_in[18];

    float* out_all  = (float*)d_out;
    float* out_last = out_all + (size_t)NL*NS*NB*2*NH;

    float *p_pad, *p_lo, *p_ro, *p_hid;
    float2* p_st;
    cudaGetSymbolAddress((void**)&p_pad, g_padded);
    cudaGetSymbolAddress((void**)&p_lo,  g_lo);
    cudaGetSymbolAddress((void**)&p_ro,  g_ro);
    cudaGetSymbolAddress((void**)&p_hid, g_hid);
    cudaGetSymbolAddress((void**)&p_st,  g_stats);

    cudaFuncSetAttribute(gemm_tf32_kernel,
                         cudaFuncAttributeMaxDynamicSharedMemorySize, SMEM_BYTES);

    int padN = NB*NSP*(NH/4);
    build_padded_kernel<<<(padN+255)/256, 256>>>(inputs, lp, rp);

    dim3 gg(NH/BN, (NB*NS)/BM);   // (4, 256)

    // Projections: lo = relu(left @ Wl + bl), ro = relu(right @ Wr + br)
    gemm_tf32_kernel<<<gg, NTHREADS, SMEM_BYTES>>>(p_pad, Wl,  bl,  p_lo, nullptr, nullptr, nullptr,
                                                   nullptr, nullptr, nullptr, NW*NH, 1, 0, 0, 0);
    gemm_tf32_kernel<<<gg, NTHREADS, SMEM_BYTES>>>(p_pad, Wr,  br_, p_ro, nullptr, nullptr, nullptr,
                                                   nullptr, nullptr, nullptr, NW*NH, 2, 0, 0, 0);

    for (int i = 0; i < NL; i++){
        float* lastp = (i == NL-1) ? out_last : nullptr;
        // left: LN fused into FF1 A-load
        ln_stats_kernel<<<(NB*NS)/8, 256>>>(p_lo, p_st);
        gemm_tf32_kernel<<<gg, NTHREADS, SMEM_BYTES>>>(p_lo, lw1 + (size_t)i*NH*NH, lb1 + i*NH, p_hid,
                                                       nullptr, nullptr, nullptr,
                                                       p_st, lg + i*NH, lbe + i*NH, NH, 3, 0, 0, 0);
        gemm_tf32_kernel<<<gg, NTHREADS, SMEM_BYTES>>>(p_hid, lw2 + (size_t)i*NH*NH, lb2 + i*NH, p_lo,
                                                       p_lo, out_all, lastp,
                                                       nullptr, nullptr, nullptr, NH, 0, 1, 0, i);
        // right
        ln_stats_kernel<<<(NB*NS)/8, 256>>>(p_ro, p_st);
        gemm_tf32_kernel<<<gg, NTHREADS, SMEM_BYTES>>>(p_ro, rw1 + (size_t)i*NH*NH, rb1 + i*NH, p_hid,
                                                       nullptr, nullptr, nullptr,
                                                       p_st, rg + i*NH, rbe + i*NH, NH, 3, 0, 0, 0);
        gemm_tf32_kernel<<<gg, NTHREADS, SMEM_BYTES>>>(p_hid, rw2 + (size_t)i*NH*NH, rb2 + i*NH, p_ro,
                                                       p_ro, out_all, lastp,
                                                       nullptr, nullptr, nullptr, NH, 0, 1, NH, i);
    }
}

// round 11
// speedup vs baseline: 1.0490x; 1.0490x over previous
#include <cuda_runtime.h>
#include <cstdint>

#define NB 16
#define NS 2048
#define NH 512
#define NW 4
#define NL 2
#define NSP (NS + 2*NW)   // 2056
#define LN_EPS 1e-5f

#define BM 128
#define BN 128
#define BK 32
#define NTHREADS 512
#define ASTR 36    // BK + 4  -> conflict-free A fragment loads
#define BSTR 136   // BN + 8  -> conflict-free B fragment loads
#define ASZ (BM*ASTR)
#define BSZ (BK*BSTR)
#define SMEM_BYTES ((2*ASZ + 2*BSZ)*4)   // ping-pong: 71680 B

// Scratch (device globals: allocation-free contract)
__device__ float  g_padded[NB*NSP*NH];
__device__ float  g_lo [NB*NS*NH];
__device__ float  g_ro [NB*NS*NH];
__device__ float  g_hid[NB*NS*NH];
__device__ float2 g_stats[NB*NS];

__device__ __forceinline__ uint32_t f2t(float x){
    uint32_t u; asm("cvt.rna.tf32.f32 %0, %1;" : "=r"(u) : "f"(x)); return u;
}

// Build padded [B, 2056, 512]
__global__ void build_padded_kernel(const float* __restrict__ inp,
                                    const float* __restrict__ lp,
                                    const float* __restrict__ rp){
    int idx = blockIdx.x*blockDim.x + threadIdx.x;
    const int H4 = NH/4;
    const int total = NB*NSP*H4;
    if (idx >= total) return;
    int h4 = idx % H4;
    int r  = (idx / H4) % NSP;
    int b  = idx / (H4*NSP);
    float4 v;
    if (r < NW)            v = reinterpret_cast<const float4*>(lp)[r*H4 + h4];
    else if (r >= NW+NS)   v = reinterpret_cast<const float4*>(rp)[(r-NW-NS)*H4 + h4];
    else                   v = reinterpret_cast<const float4*>(inp)[((size_t)b*NS + (r-NW))*H4 + h4];
    reinterpret_cast<float4*>(g_padded)[idx] = v;
}

// Per-row LN stats: mean + rstd -> g_stats. One warp per 512-float row.
__global__ void ln_stats_kernel(const float* __restrict__ x, float2* __restrict__ st){
    int row  = blockIdx.x*8 + (threadIdx.x >> 5);
    int lane = threadIdx.x & 31;
    const float4* xr = reinterpret_cast<const float4*>(x + (size_t)row*NH);
    float s = 0.f, ss = 0.f;
    #pragma unroll
    for (int i=0;i<4;i++){
        float4 v = xr[lane + i*32];
        s  += v.x + v.y + v.z + v.w;
        ss += v.x*v.x + v.y*v.y + v.z*v.z + v.w*v.w;
    }
    #pragma unroll
    for (int o=16;o>0;o>>=1){
        s  += __shfl_xor_sync(0xffffffff, s,  o);
        ss += __shfl_xor_sync(0xffffffff, ss, o);
    }
    if (lane == 0){
        float mean = s * (1.f/NH);
        float var  = ss * (1.f/NH) - mean*mean;
        st[row] = make_float2(mean, rsqrtf(var + LN_EPS));
    }
}

// tf32 tensor-core GEMM, 512 threads (16 warps), warp tile 32x32, ping-pong smem.
// amode: 0 dense A; 1 padded-left view; 2 padded-right view;
//        3 dense A with fused LayerNorm on load (stats + gvec/bvec)
// mode : 0 C = relu(acc+bias)
//        1 r = resid+acc+bias; C=r; scatter to out_all (+ optional out_last), streaming
__global__ __launch_bounds__(NTHREADS) void gemm_tf32_kernel(
    const float* __restrict__ A, const float* __restrict__ Bw, const float* __restrict__ bias,
    float* __restrict__ C, const float* __restrict__ resid,
    float* __restrict__ out_all, float* __restrict__ out_last,
    const float2* __restrict__ stats, const float* __restrict__ gvec, const float* __restrict__ bvec,
    int K, int amode, int mode, int colOff, int layer)
{
    extern __shared__ __align__(16) uint32_t sm[];
    uint32_t* Asb = sm;              // 2 * ASZ
    uint32_t* Bsb = sm + 2*ASZ;      // 2 * BSZ

    const int tid   = threadIdx.x;
    const int lane  = tid & 31;
    const int warp  = tid >> 5;
    const int group = lane >> 2;
    const int tid4  = lane & 3;

    // A: each thread stages 2 rows (tid>>3, +64), one float4 at ak
    const float* aptr[2];
    float mu[2], rs[2];
    #pragma unroll
    for (int r = 0; r < 2; r++){
        int mrow = blockIdx.y*BM + (tid>>3) + r*64;
        if (amode == 1 || amode == 2){
            int b = mrow >> 11, t = mrow & 2047;
            aptr[r] = A + ((size_t)b*NSP + t + (amode==2 ? (NW+1) : 0)) * NH;
        } else {
            aptr[r] = A + (size_t)mrow * K;
        }
        if (amode == 3){ float2 s = stats[mrow]; mu[r] = s.x; rs[r] = s.y; }
        else           { mu[r] = 0.f; rs[r] = 1.f; }
    }
    const int ak    = (tid & 7) * 4;
    const int bkrow = tid >> 5;              // 0..15 ; rows bkrow, bkrow+16
    const int bn    = (tid & 31) * 4;
    const float* bptr = Bw + blockIdx.x*BN + bn;

    float acc[2][4][4];
    #pragma unroll
    for (int i=0;i<2;i++)
      #pragma unroll
      for (int j=0;j<4;j++)
        #pragma unroll
        for (int q=0;q<4;q++) acc[i][j][q]=0.f;

    const int ntiles = K / BK;
    float4 ar[2], br[2], gv, bv;
    gv = make_float4(1.f,1.f,1.f,1.f); bv = make_float4(0.f,0.f,0.f,0.f);

    // ---- Prologue: tile 0 ----
    if (amode == 3){
        gv = *reinterpret_cast<const float4*>(gvec + ak);
        bv = *reinterpret_cast<const float4*>(bvec + ak);
    }
    #pragma unroll
    for (int r=0;r<2;r++) ar[r] = *reinterpret_cast<const float4*>(aptr[r] + ak);
    #pragma unroll
    for (int r=0;r<2;r++) br[r] = *reinterpret_cast<const float4*>(bptr + (size_t)(bkrow + r*16) * NH);
    #pragma unroll
    for (int r=0;r<2;r++){
        if (amode == 3){
            ar[r].x = fmaf(gv.x, (ar[r].x-mu[r])*rs[r], bv.x);
            ar[r].y = fmaf(gv.y, (ar[r].y-mu[r])*rs[r], bv.y);
            ar[r].z = fmaf(gv.z, (ar[r].z-mu[r])*rs[r], bv.z);
            ar[r].w = fmaf(gv.w, (ar[r].w-mu[r])*rs[r], bv.w);
        }
        int row = (tid>>3) + r*64;
        uint4 u = make_uint4(f2t(ar[r].x), f2t(ar[r].y), f2t(ar[r].z), f2t(ar[r].w));
        *reinterpret_cast<uint4*>(&Asb[row*ASTR + ak]) = u;
    }
    #pragma unroll
    for (int r=0;r<2;r++){
        int kr = bkrow + r*16;
        uint4 u = make_uint4(f2t(br[r].x), f2t(br[r].y), f2t(br[r].z), f2t(br[r].w));
        *reinterpret_cast<uint4*>(&Bsb[kr*BSTR + bn]) = u;
    }
    __syncthreads();

    const int wmb = (warp>>2)*32;   // 4 warps in M
    const int wnb = (warp&3)*32;    // 4 warps in N

    int buf = 0;
    for (int kt = 0; kt < ntiles; kt++){
        const bool more = (kt+1 < ntiles);
        if (more){
            int ko = (kt+1)*BK;
            if (amode == 3){
                gv = *reinterpret_cast<const float4*>(gvec + ko + ak);
                bv = *reinterpret_cast<const float4*>(bvec + ko + ak);
            }
            #pragma unroll
            for (int r=0;r<2;r++) ar[r] = *reinterpret_cast<const float4*>(aptr[r] + ko + ak);
            #pragma unroll
            for (int r=0;r<2;r++) br[r] = *reinterpret_cast<const float4*>(bptr + (size_t)(ko + bkrow + r*16) * NH);
        }
        const uint32_t* As = Asb + buf*ASZ;
        const uint32_t* Bs = Bsb + buf*BSZ;
        #pragma unroll
        for (int kk = 0; kk < BK; kk += 8){
            uint32_t af[2][4], bf[4][2];
            #pragma unroll
            for (int mi=0; mi<2; mi++){
                int mr = wmb + mi*16 + group;
                af[mi][0] = As[mr*ASTR     + kk + tid4];
                af[mi][1] = As[(mr+8)*ASTR + kk + tid4];
                af[mi][2] = As[mr*ASTR     + kk + tid4 + 4];
                af[mi][3] = As[(mr+8)*ASTR + kk + tid4 + 4];
            }
            #pragma unroll
            for (int ni=0; ni<4; ni++){
                int nc = wnb + ni*8 + group;
                bf[ni][0] = Bs[(kk + tid4)*BSTR     + nc];
                bf[ni][1] = Bs[(kk + tid4 + 4)*BSTR + nc];
            }
            #pragma unroll
            for (int mi=0; mi<2; mi++)
                #pragma unroll
                for (int ni=0; ni<4; ni++){
                    asm volatile(
                        "mma.sync.aligned.m16n8k8.row.col.f32.tf32.tf32.f32 "
                        "{%0,%1,%2,%3}, {%4,%5,%6,%7}, {%8,%9}, {%0,%1,%2,%3};"
                        : "+f"(acc[mi][ni][0]), "+f"(acc[mi][ni][1]),
                          "+f"(acc[mi][ni][2]), "+f"(acc[mi][ni][3])
                        : "r"(af[mi][0]), "r"(af[mi][1]), "r"(af[mi][2]), "r"(af[mi][3]),
                          "r"(bf[ni][0]), "r"(bf[ni][1]));
                }
        }
        if (more){
            uint32_t* Asn = Asb + (buf^1)*ASZ;
            uint32_t* Bsn = Bsb + (buf^1)*BSZ;
            #pragma unroll
            for (int r=0;r<2;r++){
                if (amode == 3){
                    ar[r].x = fmaf(gv.x, (ar[r].x-mu[r])*rs[r], bv.x);
                    ar[r].y = fmaf(gv.y, (ar[r].y-mu[r])*rs[r], bv.y);
                    ar[r].z = fmaf(gv.z, (ar[r].z-mu[r])*rs[r], bv.z);
                    ar[r].w = fmaf(gv.w, (ar[r].w-mu[r])*rs[r], bv.w);
                }
                int row = (tid>>3) + r*64;
                uint4 u = make_uint4(f2t(ar[r].x), f2t(ar[r].y), f2t(ar[r].z), f2t(ar[r].w));
                *reinterpret_cast<uint4*>(&Asn[row*ASTR + ak]) = u;
            }
            #pragma unroll
            for (int r=0;r<2;r++){
                int kr = bkrow + r*16;
                uint4 u = make_uint4(f2t(br[r].x), f2t(br[r].y), f2t(br[r].z), f2t(br[r].w));
                *reinterpret_cast<uint4*>(&Bsn[kr*BSTR + bn]) = u;
            }
            __syncthreads();
            buf ^= 1;
        }
    }

    // Epilogue: warp tile 32x32
    const int m0 = blockIdx.y*BM + wmb;
    const int n0 = blockIdx.x*BN + wnb;
    #pragma unroll
    for (int mi=0; mi<2; mi++){
        #pragma unroll
        for (int ni=0; ni<4; ni++){
            int rr = m0 + mi*16 + group;
            int cc = n0 + ni*8 + tid4*2;
            #pragma unroll
            for (int q=0;q<4;q++){
                int m = rr + ((q>=2) ? 8 : 0);
                int c = cc + (q&1);
                float v = acc[mi][ni][q] + bias[c];
                size_t ci = (size_t)m*NH + c;
                if (mode == 0){
                    C[ci] = fmaxf(v, 0.f);
                } else {
                    float res = resid[ci] + v;
                    C[ci] = res;
                    int b = m >> 11, s = m & 2047;
                    __stcs(&out_all[(((size_t)layer*NS + s)*NB + b)*(2*NH) + colOff + c], res);
                    if (out_last) __stcs(&out_last[((size_t)m)*(2*NH) + colOff + c], res);
                }
            }
        }
    }
}

extern "C" void kernel_launch(void* const* d_in, const int* in_sizes, int n_in,
                              void* d_out, int out_size){
    const float* inputs = (const float*)d_in[0];
    const float* lp  = (const float*)d_in[1];
    const float* rp  = (const float*)d_in[2];
    const float* Wl  = (const float*)d_in[3];
    const float* bl  = (const float*)d_in[4];
    const float* Wr  = (const float*)d_in[5];
    const float* br_ = (const float*)d_in[6];
    const float* lw1 = (const float*)d_in[7];
    const float* lb1 = (const float*)d_in[8];
    const float* lw2 = (const float*)d_in[9];
    const float* lb2 = (const float*)d_in[10];
    const float* lg  = (const float*)d_in[11];
    const float* lbe = (const float*)d_in[12];
    const float* rw1 = (const float*)d_in[13];
    const float* rb1 = (const float*)d_in[14];
    const float* rw2 = (const float*)d_in[15];
    const float* rb2 = (const float*)d_in[16];
    const float* rg  = (const float*)d_in[17];
    const float* rbe = (const float*)d_in[18];

    float* out_all  = (float*)d_out;
    float* out_last = out_all + (size_t)NL*NS*NB*2*NH;

    float *p_pad, *p_lo, *p_ro, *p_hid;
    float2* p_st;
    cudaGetSymbolAddress((void**)&p_pad, g_padded);
    cudaGetSymbolAddress((void**)&p_lo,  g_lo);
    cudaGetSymbolAddress((void**)&p_ro,  g_ro);
    cudaGetSymbolAddress((void**)&p_hid, g_hid);
    cudaGetSymbolAddress((void**)&p_st,  g_stats);

    cudaFuncSetAttribute(gemm_tf32_kernel,
                         cudaFuncAttributeMaxDynamicSharedMemorySize, SMEM_BYTES);

    int padN = NB*NSP*(NH/4);
    build_padded_kernel<<<(padN+255)/256, 256>>>(inputs, lp, rp);

    dim3 gg(NH/BN, (NB*NS)/BM);   // (4, 256)

    // Projections: lo = relu(left @ Wl + bl), ro = relu(right @ Wr + br)
    gemm_tf32_kernel<<<gg, NTHREADS, SMEM_BYTES>>>(p_pad, Wl,  bl,  p_lo, nullptr, nullptr, nullptr,
                                                   nullptr, nullptr, nullptr, NW*NH, 1, 0, 0, 0);
    gemm_tf32_kernel<<<gg, NTHREADS, SMEM_BYTES>>>(p_pad, Wr,  br_, p_ro, nullptr, nullptr, nullptr,
                                                   nullptr, nullptr, nullptr, NW*NH, 2, 0, 0, 0);

    for (int i = 0; i < NL; i++){
        float* lastp = (i == NL-1) ? out_last : nullptr;
        // left: LN fused into FF1 A-load
        ln_stats_kernel<<<(NB*NS)/8, 256>>>(p_lo, p_st);
        gemm_tf32_kernel<<<gg, NTHREADS, SMEM_BYTES>>>(p_lo, lw1 + (size_t)i*NH*NH, lb1 + i*NH, p_hid,
                                                       nullptr, nullptr, nullptr,
                                                       p_st, lg + i*NH, lbe + i*NH, NH, 3, 0, 0, 0);
        gemm_tf32_kernel<<<gg, NTHREADS, SMEM_BYTES>>>(p_hid, lw2 + (size_t)i*NH*NH, lb2 + i*NH, p_lo,
                                                       p_lo, out_all, lastp,
                                                       nullptr, nullptr, nullptr, NH, 0, 1, 0, i);
        // right
        ln_stats_kernel<<<(NB*NS)/8, 256>>>(p_ro, p_st);
        gemm_tf32_kernel<<<gg, NTHREADS, SMEM_BYTES>>>(p_ro, rw1 + (size_t)i*NH*NH, rb1 + i*NH, p_hid,
                                                       nullptr, nullptr, nullptr,
                                                       p_st, rg + i*NH, rbe + i*NH, NH, 3, 0, 0, 0);
        gemm_tf32_kernel<<<gg, NTHREADS, SMEM_BYTES>>>(p_hid, rw2 + (size_t)i*NH*NH, rb2 + i*NH, p_ro,
                                                       p_ro, out_all, lastp,
                                                       nullptr, nullptr, nullptr, NH, 0, 1, NH, i);
    }
}